// round 1
// baseline (speedup 1.0000x reference)
#include <cuda_runtime.h>
#include <cuda_bf16.h>
#include <stdint.h>

// Problem constants (from reference): T=10, C=3, H=512, W=512, PT=2, PS=7
// patches: [Q, PT, C, PS, PS] float32, queryInds: [Q,3] int32 (t,h,w)
// out: [T, C, H, W] float32

#define PS 7
#define PT 2
#define CCH 3
#define HH 512
#define WW 512
#define HW (HH * WW)
#define ROWS_PER_Q (PT * CCH * PS)  // 42

__global__ void __launch_bounds__(256)
scatter_rows_kernel(const float* __restrict__ patches,
                    const int*   __restrict__ qinds,
                    float*       __restrict__ out,
                    int nRows)
{
    int rid = blockIdx.x * blockDim.x + threadIdx.x;
    if (rid >= nRows) return;

    // decompose rid -> (q, dt, c, di)
    int q    = rid / ROWS_PER_Q;
    int rem  = rid - q * ROWS_PER_Q;          // 0..41
    int dt   = rem / (CCH * PS);              // 0..1
    int rem2 = rem - dt * (CCH * PS);         // 0..20
    int c    = rem2 / PS;                     // 0..2
    int di   = rem2 - c * PS;                 // 0..6

    int t = __ldg(&qinds[3 * q + 0]);
    int h = __ldg(&qinds[3 * q + 1]);
    int w = __ldg(&qinds[3 * q + 2]);

    int base = ((t + dt) * CCH + c) * HW + (h + di) * WW + w;
    const float* src = patches + (long long)rid * PS;

#pragma unroll
    for (int dj = 0; dj < PS; ++dj) {
        atomicAdd(out + base + dj, __ldg(&src[dj]));
    }
}

extern "C" void kernel_launch(void* const* d_in, const int* in_sizes, int n_in,
                              void* d_out, int out_size)
{
    const float* vid     = (const float*)d_in[0];
    const float* patches = (const float*)d_in[1];
    const int*   qinds   = (const int*)  d_in[2];
    float*       out     = (float*)d_out;

    int Q = in_sizes[2] / 3;
    int nRows = Q * ROWS_PER_Q;

    // initialize output with vid2fill (d_out is poisoned)
    cudaMemcpyAsync(out, vid, (size_t)out_size * sizeof(float),
                    cudaMemcpyDeviceToDevice, 0);

    int threads = 256;
    int blocks = (nRows + threads - 1) / threads;
    scatter_rows_kernel<<<blocks, threads, 0, 0>>>(patches, qinds, out, nRows);
}

// round 2
// speedup vs baseline: 1.9614x; 1.9614x over previous
#include <cuda_runtime.h>
#include <cuda_bf16.h>
#include <stdint.h>

// T=10, C=3, H=512, W=512, PT=2, PS=7
// patches: [Q, PT, C, PS, PS] f32; queryInds: [Q,3] i32 (t,h,w); out: [T,C,H,W] f32

#define PS 7
#define PT 2
#define CCH 3
#define HH 512
#define WW 512
#define HW (HH * WW)
#define ROWS_PER_Q (PT * CCH * PS)  // 42

__device__ __forceinline__ void red1(float* p, float v) {
    asm volatile("red.global.add.f32 [%0], %1;" :: "l"(p), "f"(v) : "memory");
}
__device__ __forceinline__ void red2(float* p, float a, float b) {
    asm volatile("red.global.add.v2.f32 [%0], {%1,%2};" :: "l"(p), "f"(a), "f"(b) : "memory");
}
__device__ __forceinline__ void red4(float* p, float a, float b, float c, float d) {
    asm volatile("red.global.add.v4.f32 [%0], {%1,%2,%3,%4};"
                 :: "l"(p), "f"(a), "f"(b), "f"(c), "f"(d) : "memory");
}

__global__ void __launch_bounds__(256)
scatter_rows_vec_kernel(const float* __restrict__ patches,
                        const int*   __restrict__ qinds,
                        float*       __restrict__ out,
                        int nRows)
{
    int rid = blockIdx.x * blockDim.x + threadIdx.x;
    if (rid >= nRows) return;

    // decompose rid -> (q, dt, c, di)
    int q    = rid / ROWS_PER_Q;
    int rem  = rid - q * ROWS_PER_Q;          // 0..41
    int dt   = rem / (CCH * PS);              // 0..1
    int rem2 = rem - dt * (CCH * PS);         // 0..20
    int c    = rem2 / PS;                     // 0..2
    int di   = rem2 - c * PS;                 // 0..6

    int t = __ldg(&qinds[3 * q + 0]);
    int h = __ldg(&qinds[3 * q + 1]);
    int w = __ldg(&qinds[3 * q + 2]);

    int base = ((t + dt) * CCH + c) * HW + (h + di) * WW + w;
    const float* src = patches + (long long)rid * PS;

    float v[PS];
#pragma unroll
    for (int j = 0; j < PS; ++j) v[j] = __ldg(&src[j]);

    float* p = out + base;
    int a = base & 3;

    // cover 7 contiguous floats with exactly 3 RED requests, alignment-safe
    switch (a) {
    case 0:
        red4(p + 0, v[0], v[1], v[2], v[3]);
        red2(p + 4, v[4], v[5]);
        red1(p + 6, v[6]);
        break;
    case 1:
        red1(p + 0, v[0]);
        red2(p + 1, v[1], v[2]);
        red4(p + 3, v[3], v[4], v[5], v[6]);
        break;
    case 2:
        red2(p + 0, v[0], v[1]);
        red4(p + 2, v[2], v[3], v[4], v[5]);
        red1(p + 6, v[6]);
        break;
    default: // 3
        red1(p + 0, v[0]);
        red4(p + 1, v[1], v[2], v[3], v[4]);
        red2(p + 5, v[5], v[6]);
        break;
    }
}

extern "C" void kernel_launch(void* const* d_in, const int* in_sizes, int n_in,
                              void* d_out, int out_size)
{
    const float* vid     = (const float*)d_in[0];
    const float* patches = (const float*)d_in[1];
    const int*   qinds   = (const int*)  d_in[2];
    float*       out     = (float*)d_out;

    int Q = in_sizes[2] / 3;
    int nRows = Q * ROWS_PER_Q;

    cudaMemcpyAsync(out, vid, (size_t)out_size * sizeof(float),
                    cudaMemcpyDeviceToDevice, 0);

    int threads = 256;
    int blocks = (nRows + threads - 1) / threads;
    scatter_rows_vec_kernel<<<blocks, threads, 0, 0>>>(patches, qinds, out, nRows);
}

// round 3
// speedup vs baseline: 2.1865x; 1.1148x over previous
#include <cuda_runtime.h>
#include <cuda_bf16.h>
#include <stdint.h>

// T=10, C=3, H=512, W=512, PT=2, PS=7
// patches: [Q, PT, C, PS, PS] f32; queryInds: [Q,3] i32 (t,h,w); out: [T,C,H,W] f32

#define PS 7
#define PT 2
#define CCH 3
#define HH 512
#define WW 512
#define HW (HH * WW)
#define ROWS_PER_Q (PT * CCH * PS)  // 42

__device__ __forceinline__ void red1(float* p, float v) {
    asm volatile("red.global.add.f32 [%0], %1;" :: "l"(p), "f"(v) : "memory");
}
__device__ __forceinline__ void red2(float* p, float a, float b) {
    asm volatile("red.global.add.v2.f32 [%0], {%1,%2};" :: "l"(p), "f"(a), "f"(b) : "memory");
}
__device__ __forceinline__ void red4(float* p, float a, float b, float c, float d) {
    asm volatile("red.global.add.v4.f32 [%0], {%1,%2,%3,%4};"
                 :: "l"(p), "f"(a), "f"(b), "f"(c), "f"(d) : "memory");
}

__global__ void __launch_bounds__(256)
scatter_rows_pad_kernel(const float* __restrict__ patches,
                        const int*   __restrict__ qinds,
                        float*       __restrict__ out,
                        int nRows, int nTotal)
{
    int rid = blockIdx.x * blockDim.x + threadIdx.x;
    if (rid >= nRows) return;

    // decompose rid -> (q, dt, c, di)
    int q    = rid / ROWS_PER_Q;
    int rem  = rid - q * ROWS_PER_Q;          // 0..41
    int dt   = rem / (CCH * PS);              // 0..1
    int rem2 = rem - dt * (CCH * PS);         // 0..20
    int c    = rem2 / PS;                     // 0..2
    int di   = rem2 - c * PS;                 // 0..6

    int t = __ldg(&qinds[3 * q + 0]);
    int h = __ldg(&qinds[3 * q + 1]);
    int w = __ldg(&qinds[3 * q + 2]);

    int base = ((t + dt) * CCH + c) * HW + (h + di) * WW + w;
    const float* src = patches + (long long)rid * PS;

    float v[PS];
#pragma unroll
    for (int j = 0; j < PS; ++j) v[j] = __ldg(&src[j]);

    float* p = out + base;
    int a = base & 3;

    switch (a) {
    case 0:
        if (base + 8 <= nTotal) {
            // [0..3] + [4..7] with one zero pad at +7
            red4(p + 0, v[0], v[1], v[2], v[3]);
            red4(p + 4, v[4], v[5], v[6], 0.0f);
        } else {
            red4(p + 0, v[0], v[1], v[2], v[3]);
            red2(p + 4, v[4], v[5]);
            red1(p + 6, v[6]);
        }
        break;
    case 1:
        // [-1..2] with zero pad at -1, + [3..6]; base>=1 guaranteed (base&3==1)
        red4(p - 1, 0.0f, v[0], v[1], v[2]);
        red4(p + 3, v[3], v[4], v[5], v[6]);
        break;
    case 2:
        red2(p + 0, v[0], v[1]);
        red4(p + 2, v[2], v[3], v[4], v[5]);
        red1(p + 6, v[6]);
        break;
    default: // 3
        red1(p + 0, v[0]);
        red4(p + 1, v[1], v[2], v[3], v[4]);
        red2(p + 5, v[5], v[6]);
        break;
    }
}

extern "C" void kernel_launch(void* const* d_in, const int* in_sizes, int n_in,
                              void* d_out, int out_size)
{
    const float* vid     = (const float*)d_in[0];
    const float* patches = (const float*)d_in[1];
    const int*   qinds   = (const int*)  d_in[2];
    float*       out     = (float*)d_out;

    int Q = in_sizes[2] / 3;
    int nRows = Q * ROWS_PER_Q;

    cudaMemcpyAsync(out, vid, (size_t)out_size * sizeof(float),
                    cudaMemcpyDeviceToDevice, 0);

    int threads = 256;
    int blocks = (nRows + threads - 1) / threads;
    scatter_rows_pad_kernel<<<blocks, threads, 0, 0>>>(patches, qinds, out,
                                                       nRows, out_size);
}